// round 7
// baseline (speedup 1.0000x reference)
#include <cuda_runtime.h>
#include <cstdint>

#define BB    64
#define TOPK  2
#define EE    16
#define CC    1024
#define KK    4096
#define NTOK  (BB * TOPK)     // 128

#define WARPS  8
#define RPW    4               // rows per warp
#define TCH    8               // tokens per chunk
#define CTILE  (WARPS * RPW)   // 32 rows per CTA
#define K4     (KK / 4)        // 1024 float4 per row
#define JITERS (K4 / 32)       // 32 k-steps (512B per row per step)
#define NSTAGE 5

// per-warp private w ring: [WARPS][NSTAGE][RPW][32] float4
#define WSLOT_F4  (RPW * 32)                     // 128 f4 = 2KB per stage per warp
#define DYN_BYTES (WARPS * NSTAGE * WSLOT_F4 * 16)   // 81920

__device__ float g_tmp[NTOK * CC];

// ---- PTX helpers -----------------------------------------------------------
__device__ __forceinline__ void cp16(uint32_t dst, const void* src) {
    asm volatile("cp.async.cg.shared.global [%0], [%1], 16;"
                 :: "r"(dst), "l"(src) : "memory");
}
__device__ __forceinline__ void cp_commit() {
    asm volatile("cp.async.commit_group;" ::: "memory");
}
template <int N>
__device__ __forceinline__ void cp_wait() {
    asm volatile("cp.async.wait_group %0;" :: "n"(N) : "memory");
}
__device__ __forceinline__ void ffma2(unsigned long long& acc,
                                      unsigned long long w,
                                      unsigned long long a) {
    asm("fma.rn.f32x2 %0, %1, %2, %0;" : "+l"(acc) : "l"(w), "l"(a));
}
__device__ __forceinline__ float pair_sum(unsigned long long p) {
    float lo, hi;
    asm("mov.b64 {%0, %1}, %2;" : "=f"(lo), "=f"(hi) : "l"(p));
    return lo + hi;
}

// ---------------------------------------------------------------------------
// Grouped expert matvec — warp-decoupled streaming.
// Grid (CC/CTILE=32, EE=16, 2). Block 256 (8 warps), occ 2.
// Each warp owns rows c0+warp*4..+3 and streams them through a PRIVATE
// 5-stage cp.async smem ring (each lane reads only bytes it wrote -> no
// barriers, no cross-warp coupling in the j-loop). Activations are read
// directly with LDG (identical addresses across warps -> L1/L2 hot).
// ---------------------------------------------------------------------------
__global__ void __launch_bounds__(256, 2)
matvec(const float* __restrict__ act,
       const float* __restrict__ W,
       const int*  __restrict__ eidx) {
    extern __shared__ float4 ring[];   // [WARPS][NSTAGE][RPW][32]

    __shared__ int se[NTOK];
    __shared__ int stok[NTOK];

    const int tid = threadIdx.x;
    const int e   = blockIdx.y;

    if (tid < NTOK) se[tid] = eidx[tid];
    __syncthreads();
    int mine = (tid < NTOK) && (se[tid] == e);
    if (mine) {
        int pos = 0;
        for (int j = 0; j < tid; ++j) pos += (se[j] == e) ? 1 : 0;
        stok[pos] = tid;
    }
    const int cnt = __syncthreads_count(mine);
    if (cnt == 0) return;

    const int warp = tid >> 5;
    const int lane = tid & 31;
    const int c0   = blockIdx.x * CTILE + warp * RPW;

    // w source rows for this warp (lane column baked in)
    const float4* __restrict__ wsrc =
        reinterpret_cast<const float4*>(W) + ((size_t)(e * CC + c0)) * K4 + lane;
    // this warp's private ring (lane's own 16B slots)
    float4* myring = ring + (size_t)warp * NSTAGE * WSLOT_F4;
    const uint32_t dst0 =
        (uint32_t)__cvta_generic_to_shared(myring) + lane * 16;

    const float4* __restrict__ a4 = reinterpret_cast<const float4*>(act);

    for (int t0 = blockIdx.z * TCH; t0 < cnt; t0 += 2 * TCH) {
        int aoff[TCH];
#pragma unroll
        for (int t = 0; t < TCH; ++t) {
            int tt  = (t0 + t < cnt) ? (t0 + t) : (cnt - 1);   // tail clamp
            aoff[t] = stok[tt] * K4 + lane;
        }

        unsigned long long acc[RPW][TCH];
#pragma unroll
        for (int r = 0; r < RPW; ++r)
#pragma unroll
            for (int t = 0; t < TCH; ++t) acc[r][t] = 0ull;

        // ---- prime stages 0 .. NSTAGE-2 (per-warp, no barrier) ----
#pragma unroll
        for (int s = 0; s < NSTAGE - 1; ++s) {
            const uint32_t d = dst0 + s * (WSLOT_F4 * 16);
#pragma unroll
            for (int r = 0; r < RPW; ++r)
                cp16(d + r * 512, wsrc + (size_t)r * K4 + s * 32);
            cp_commit();
        }

#pragma unroll 1
        for (int j = 0; j < JITERS; ++j) {
            cp_wait<NSTAGE - 2>();          // own groups: stage j ready

            // refill slot (j-1)%NSTAGE for step j+NSTAGE-1 (private -> safe)
            const int jf = j + NSTAGE - 1;
            if (jf < JITERS) {
                const uint32_t d = dst0 + (jf % NSTAGE) * (WSLOT_F4 * 16);
#pragma unroll
                for (int r = 0; r < RPW; ++r)
                    cp16(d + r * 512, wsrc + (size_t)r * K4 + jf * 32);
            }
            cp_commit();                    // always commit to keep counts aligned

            // consume own stage j%NSTAGE (LDS.128, conflict-free)
            const ulonglong2* wb = reinterpret_cast<const ulonglong2*>(
                myring + (size_t)(j % NSTAGE) * WSLOT_F4);
            ulonglong2 wv[RPW];
#pragma unroll
            for (int r = 0; r < RPW; ++r) wv[r] = wb[r * 32 + lane];

            // activations: 2 batches of 4 LDG.128 (bounds reg pressure)
#pragma unroll
            for (int th = 0; th < 2; ++th) {
                ulonglong2 av[4];
#pragma unroll
                for (int t = 0; t < 4; ++t)
                    av[t] = reinterpret_cast<const ulonglong2*>(a4)
                                [aoff[th * 4 + t] + j * 32];
#pragma unroll
                for (int t = 0; t < 4; ++t)
#pragma unroll
                    for (int r = 0; r < RPW; ++r) {
                        ffma2(acc[r][th * 4 + t], wv[r].x, av[t].x);
                        ffma2(acc[r][th * 4 + t], wv[r].y, av[t].y);
                    }
            }
        }

        // ---- fold, warp-reduce, store ----
#pragma unroll
        for (int r = 0; r < RPW; ++r) {
#pragma unroll
            for (int t = 0; t < TCH; ++t) {
                float v = pair_sum(acc[r][t]);
                v += __shfl_xor_sync(0xFFFFFFFFu, v, 16);
                v += __shfl_xor_sync(0xFFFFFFFFu, v, 8);
                v += __shfl_xor_sync(0xFFFFFFFFu, v, 4);
                v += __shfl_xor_sync(0xFFFFFFFFu, v, 2);
                v += __shfl_xor_sync(0xFFFFFFFFu, v, 1);
                if (lane == 0 && (t0 + t) < cnt)
                    g_tmp[stok[t0 + t] * CC + c0 + r] = v;
            }
        }
        // no barrier: ring is warp-private, a is global
    }
}

// ---------------------------------------------------------------------------
__global__ void finalize(const float* __restrict__ residual,
                         const float* __restrict__ bias,
                         const float* __restrict__ ew,
                         const int*  __restrict__ eidx,
                         float* __restrict__ out) {
    const int idx = blockIdx.x * blockDim.x + threadIdx.x;   // over BB*CC/4
    const int b   = idx / (CC / 4);
    const int c4  = idx % (CC / 4);

    const float4* r4 = reinterpret_cast<const float4*>(residual);
    const float4* b4 = reinterpret_cast<const float4*>(bias);
    const float4* t4 = reinterpret_cast<const float4*>(g_tmp);
    float4 v = r4[b * (CC / 4) + c4];
#pragma unroll
    for (int s = 0; s < TOPK; ++s) {
        const int   e = eidx[b * TOPK + s];
        const float w = ew[b * TOPK + s];
        float4 t  = t4[(b * TOPK + s) * (CC / 4) + c4];
        float4 bb = b4[e * (CC / 4) + c4];
        v.x += w * (t.x + bb.x);
        v.y += w * (t.y + bb.y);
        v.z += w * (t.z + bb.z);
        v.w += w * (t.w + bb.w);
    }
    reinterpret_cast<float4*>(out)[b * (CC / 4) + c4] = v;
}

__global__ void epilogue_nop() {}

// ---------------------------------------------------------------------------
extern "C" void kernel_launch(void* const* d_in, const int* in_sizes, int n_in,
                              void* d_out, int out_size) {
    const float* activated      = (const float*)d_in[0];
    const int*   expert_indices = (const int*)  d_in[1];
    const float* expert_weights = (const float*)d_in[2];
    const float* mlp2_weight    = (const float*)d_in[3];
    const float* mlp2_bias      = (const float*)d_in[4];
    const float* residual_x     = (const float*)d_in[5];
    float*       out            = (float*)d_out;

    static bool attr_done = false;
    if (!attr_done) {
        cudaFuncSetAttribute(matvec, cudaFuncAttributeMaxDynamicSharedMemorySize,
                             DYN_BYTES);
        attr_done = true;
    }

    dim3 grid(CC / CTILE, EE, 2);
    matvec<<<grid, WARPS * 32, DYN_BYTES>>>(activated, mlp2_weight,
                                            expert_indices);

    finalize<<<(BB * CC / 4) / 256, 256>>>(residual_x, mlp2_bias,
                                           expert_weights, expert_indices, out);
    epilogue_nop<<<1, 1>>>();
}

// round 8
// speedup vs baseline: 1.4719x; 1.4719x over previous
#include <cuda_runtime.h>
#include <cstdint>

#define BB    64
#define TOPK  2
#define EE    16
#define CC    1024
#define KK    4096
#define NTOK  (BB * TOPK)     // 128

#define WARPS  8
#define RPW    4               // rows per warp
#define TCH    8               // tokens per work item
#define CTILE  (WARPS * RPW)   // 32 rows per item
#define K4     (KK / 4)        // 1024 float4 per row
#define JITERS (K4 / 32)       // 32 k-steps (512B per row per step)
#define NSTAGE 5
#define NCTAS  296             // 2 per SM x 148 SMs

// stage = w [CTILE][32] f4 + a [TCH][32] f4
#define W_ST_F4   (CTILE * 32)
#define A_ST_F4   (TCH * 32)
#define DYN_BYTES (NSTAGE * (W_ST_F4 + A_ST_F4) * 16)   // 102400

__device__ float g_tmp[NTOK * CC];
__device__ int   g_ctr = 0;     // work counter; reset by finalize each replay

// ---- PTX helpers -----------------------------------------------------------
__device__ __forceinline__ void cp16(uint32_t dst, const void* src) {
    asm volatile("cp.async.cg.shared.global [%0], [%1], 16;"
                 :: "r"(dst), "l"(src) : "memory");
}
__device__ __forceinline__ void cp_commit() {
    asm volatile("cp.async.commit_group;" ::: "memory");
}
template <int N>
__device__ __forceinline__ void cp_wait() {
    asm volatile("cp.async.wait_group %0;" :: "n"(N) : "memory");
}
__device__ __forceinline__ void ffma2(unsigned long long& acc,
                                      unsigned long long w,
                                      unsigned long long a) {
    asm("fma.rn.f32x2 %0, %1, %2, %0;" : "+l"(acc) : "l"(w), "l"(a));
}
__device__ __forceinline__ float pair_sum(unsigned long long p) {
    float lo, hi;
    asm("mov.b64 {%0, %1}, %2;" : "=f"(lo), "=f"(hi) : "l"(p));
    return lo + hi;
}

// ---------------------------------------------------------------------------
// Persistent grouped expert matvec. Grid 296, block 256 (8 warps), occ 2.
// Each CTA builds the per-expert token lists + work-item table in smem,
// then pulls items (expert-chunk, c-tile) off a global atomic counter.
// Per item: R5's proven 5-stage cp.async pipeline (w 16KB + a 4KB per stage).
// ---------------------------------------------------------------------------
__global__ void __launch_bounds__(256, 2)
matvec(const float* __restrict__ act,
       const float* __restrict__ W,
       const int*  __restrict__ eidx) {
    extern __shared__ float4 dyn[];
    float4* w_st = dyn;                       // [NSTAGE][CTILE][32]
    float4* a_st = dyn + NSTAGE * W_ST_F4;    // [NSTAGE][TCH][32]

    __shared__ int se[NTOK];
    __shared__ int stok[NTOK];                // tokens sorted by expert
    __shared__ int scnt[EE], soffs[EE];
    __shared__ int sitems[64];                // (e<<8)|t0 per chunk
    __shared__ int s_nwork, s_i;

    const int tid  = threadIdx.x;
    const int warp = tid >> 5;
    const int lane = tid & 31;

    // ---- per-CTA list + work-table build (cheap, deterministic) ----
    if (tid < NTOK) se[tid] = eidx[tid];
    __syncthreads();
    if (tid < EE) {
        int c = 0;
        for (int j = 0; j < NTOK; ++j) c += (se[j] == tid) ? 1 : 0;
        scnt[tid] = c;
    }
    __syncthreads();
    if (tid == 0) {
        int o = 0;
        for (int e = 0; e < EE; ++e) { soffs[e] = o; o += scnt[e]; }
        int u = 0;
        for (int e = 0; e < EE; ++e)
            for (int t0 = 0; t0 < scnt[e]; t0 += TCH)
                sitems[u++] = (e << 8) | t0;
        s_nwork = u * 32;                      // 32 c-tiles per chunk
    }
    __syncthreads();
    if (tid < NTOK) {
        int e = se[tid], r = 0;
        for (int j = 0; j < tid; ++j) r += (se[j] == e) ? 1 : 0;
        stok[soffs[e] + r] = tid;
    }
    __syncthreads();
    const int nwork = s_nwork;

    // ---- persistent work loop ----
    for (;;) {
        if (tid == 0) s_i = atomicAdd(&g_ctr, 1);
        __syncthreads();
        const int i = s_i;
        if (i >= nwork) break;

        const int it  = sitems[i >> 5];
        const int e   = it >> 8;
        const int t0  = it & 255;
        const int c0  = (i & 31) * CTILE;
        const int cnt = scnt[e];
        const int off = soffs[e];

        // fill sources: w rows {c0+warp+8i}, a token slot t0+warp (clamped)
        const float4* __restrict__ wsrc =
            reinterpret_cast<const float4*>(W) +
            ((size_t)(e * CC + c0 + warp)) * K4 + lane;
        int myt = t0 + warp;
        if (myt >= cnt) myt = cnt - 1;
        const float4* asrc =
            reinterpret_cast<const float4*>(act) +
            (size_t)stok[off + myt] * K4 + lane;

        const uint32_t wdst0 =
            (uint32_t)__cvta_generic_to_shared(&w_st[(size_t)warp * 32 + lane]);
        const uint32_t adst0 =
            (uint32_t)__cvta_generic_to_shared(&a_st[(size_t)warp * 32 + lane]);

        unsigned long long acc[RPW][TCH];
#pragma unroll
        for (int r = 0; r < RPW; ++r)
#pragma unroll
            for (int t = 0; t < TCH; ++t) acc[r][t] = 0ull;

        // ---- prime stages 0 .. NSTAGE-2 ----
#pragma unroll
        for (int s = 0; s < NSTAGE - 1; ++s) {
            uint32_t wd = wdst0 + s * (W_ST_F4 * 16);
#pragma unroll
            for (int q = 0; q < 4; ++q)
                cp16(wd + q * (8 * 32 * 16), wsrc + (size_t)(8 * q) * K4 + s * 32);
            cp16(adst0 + s * (A_ST_F4 * 16), asrc + s * 32);
            cp_commit();
        }

#pragma unroll 1
        for (int j = 0; j < JITERS; ++j) {
            cp_wait<NSTAGE - 2>();           // oldest groups drained: stage j ready
            __syncthreads();

            const int jf = j + NSTAGE - 1;
            if (jf < JITERS) {
                const int sf = jf % NSTAGE;
                uint32_t wd = wdst0 + sf * (W_ST_F4 * 16);
#pragma unroll
                for (int q = 0; q < 4; ++q)
                    cp16(wd + q * (8 * 32 * 16), wsrc + (size_t)(8 * q) * K4 + jf * 32);
                cp16(adst0 + sf * (A_ST_F4 * 16), asrc + jf * 32);
            }
            cp_commit();                     // every j: keeps group counts aligned

            // ---- consume stage j%NSTAGE ----
            const int s = j % NSTAGE;
            const ulonglong2* wb = reinterpret_cast<const ulonglong2*>(
                w_st + (size_t)s * W_ST_F4 + warp * (RPW * 32));
            const ulonglong2* ab = reinterpret_cast<const ulonglong2*>(
                a_st + (size_t)s * A_ST_F4);

            ulonglong2 wv[RPW];
#pragma unroll
            for (int r = 0; r < RPW; ++r) wv[r] = wb[r * 32 + lane];
#pragma unroll
            for (int t = 0; t < TCH; ++t) {
                ulonglong2 av = ab[t * 32 + lane];
#pragma unroll
                for (int r = 0; r < RPW; ++r) {
                    ffma2(acc[r][t], wv[r].x, av.x);
                    ffma2(acc[r][t], wv[r].y, av.y);
                }
            }
        }

        // ---- fold, warp-reduce, store raw dots ----
#pragma unroll
        for (int r = 0; r < RPW; ++r) {
#pragma unroll
            for (int t = 0; t < TCH; ++t) {
                float v = pair_sum(acc[r][t]);
                v += __shfl_xor_sync(0xFFFFFFFFu, v, 16);
                v += __shfl_xor_sync(0xFFFFFFFFu, v, 8);
                v += __shfl_xor_sync(0xFFFFFFFFu, v, 4);
                v += __shfl_xor_sync(0xFFFFFFFFu, v, 2);
                v += __shfl_xor_sync(0xFFFFFFFFu, v, 1);
                if (lane == 0 && (t0 + t) < cnt)
                    g_tmp[stok[off + t0 + t] * CC + c0 + warp * RPW + r] = v;
            }
        }
        __syncthreads();   // stage reads done before next item re-primes
    }
}

// ---------------------------------------------------------------------------
// finalize: out = residual + sum_s ew * (tmp + bias[e]); also resets g_ctr
// for the next graph replay (runs after matvec in stream order).
// ---------------------------------------------------------------------------
__global__ void finalize(const float* __restrict__ residual,
                         const float* __restrict__ bias,
                         const float* __restrict__ ew,
                         const int*  __restrict__ eidx,
                         float* __restrict__ out) {
    const int idx = blockIdx.x * blockDim.x + threadIdx.x;   // over BB*CC/4
    const int b   = idx / (CC / 4);
    const int c4  = idx % (CC / 4);

    if (idx == 0) g_ctr = 0;   // reset work counter for next replay

    const float4* r4 = reinterpret_cast<const float4*>(residual);
    const float4* b4 = reinterpret_cast<const float4*>(bias);
    const float4* t4 = reinterpret_cast<const float4*>(g_tmp);
    float4 v = r4[b * (CC / 4) + c4];
#pragma unroll
    for (int s = 0; s < TOPK; ++s) {
        const int   e = eidx[b * TOPK + s];
        const float w = ew[b * TOPK + s];
        float4 t  = t4[(b * TOPK + s) * (CC / 4) + c4];
        float4 bb = b4[e * (CC / 4) + c4];
        v.x += w * (t.x + bb.x);
        v.y += w * (t.y + bb.y);
        v.z += w * (t.z + bb.z);
        v.w += w * (t.w + bb.w);
    }
    reinterpret_cast<float4*>(out)[b * (CC / 4) + c4] = v;
}

// ---------------------------------------------------------------------------
extern "C" void kernel_launch(void* const* d_in, const int* in_sizes, int n_in,
                              void* d_out, int out_size) {
    const float* activated      = (const float*)d_in[0];
    const int*   expert_indices = (const int*)  d_in[1];
    const float* expert_weights = (const float*)d_in[2];
    const float* mlp2_weight    = (const float*)d_in[3];
    const float* mlp2_bias      = (const float*)d_in[4];
    const float* residual_x     = (const float*)d_in[5];
    float*       out            = (float*)d_out;

    static bool attr_done = false;
    if (!attr_done) {
        cudaFuncSetAttribute(matvec, cudaFuncAttributeMaxDynamicSharedMemorySize,
                             DYN_BYTES);
        attr_done = true;
    }

    matvec<<<NCTAS, WARPS * 32, DYN_BYTES>>>(activated, mlp2_weight,
                                             expert_indices);

    finalize<<<(BB * CC / 4) / 256, 256>>>(residual_x, mlp2_bias,
                                           expert_weights, expert_indices, out);
}

// round 9
// speedup vs baseline: 1.7642x; 1.1986x over previous
#include <cuda_runtime.h>
#include <cstdint>

#define BB    64
#define TOPK  2
#define EE    16
#define CC    1024
#define KK    4096
#define NTOK  (BB * TOPK)     // 128

#define WARPS  8
#define RPW    4               // rows per warp
#define TCH    8               // tokens per chunk
#define CTILE  (WARPS * RPW)   // 32 rows per CTA
#define K4     (KK / 4)        // 1024 float4 per row
#define JITERS (K4 / 32)       // 32 k-steps (512B per row per step)
#define NSTAGE 5

// stage = w [CTILE][32] f4 + a [TCH][32] f4
#define W_ST_F4   (CTILE * 32)
#define A_ST_F4   (TCH * 32)
#define DYN_BYTES (NSTAGE * (W_ST_F4 + A_ST_F4) * 16)   // 102400

__device__ float g_tmp[NTOK * CC];

// ---- PTX helpers -----------------------------------------------------------
__device__ __forceinline__ void cp16(uint32_t dst, const void* src) {
    asm volatile("cp.async.cg.shared.global [%0], [%1], 16;"
                 :: "r"(dst), "l"(src) : "memory");
}
__device__ __forceinline__ void cp_commit() {
    asm volatile("cp.async.commit_group;" ::: "memory");
}
template <int N>
__device__ __forceinline__ void cp_wait() {
    asm volatile("cp.async.wait_group %0;" :: "n"(N) : "memory");
}
__device__ __forceinline__ void ffma2(unsigned long long& acc,
                                      unsigned long long w,
                                      unsigned long long a) {
    asm("fma.rn.f32x2 %0, %1, %2, %0;" : "+l"(acc) : "l"(w), "l"(a));
}
__device__ __forceinline__ float pair_sum(unsigned long long p) {
    float lo, hi;
    asm("mov.b64 {%0, %1}, %2;" : "=f"(lo), "=f"(hi) : "l"(p));
    return lo + hi;
}

// ---------------------------------------------------------------------------
// Grouped expert matvec, 5-stage cp.async pipeline for BOTH w and a.
// Grid (2, CC/CTILE=32, EE=16): x = token-chunk slot (FASTEST dim so the two
// chunk-CTAs sharing the same weight tile are bid-adjacent -> co-scheduled in
// the same wave -> second w read hits L2 instead of DRAM), y = c-tile,
// z = expert. Block 256 (8 warps), occ 2.
// ---------------------------------------------------------------------------
__global__ void __launch_bounds__(256, 2)
matvec(const float* __restrict__ act,
       const float* __restrict__ W,
       const int*  __restrict__ eidx) {
    extern __shared__ float4 dyn[];
    float4* w_st = dyn;                       // [NSTAGE][CTILE][32]
    float4* a_st = dyn + NSTAGE * W_ST_F4;    // [NSTAGE][TCH][32]

    __shared__ int se[NTOK];
    __shared__ int stok[NTOK];

    const int tid = threadIdx.x;
    const int e   = blockIdx.z;

    if (tid < NTOK) se[tid] = eidx[tid];
    __syncthreads();
    int mine = (tid < NTOK) && (se[tid] == e);
    if (mine) {
        int pos = 0;
        for (int j = 0; j < tid; ++j) pos += (se[j] == e) ? 1 : 0;
        stok[pos] = tid;
    }
    const int cnt = __syncthreads_count(mine);
    if (cnt == 0) return;

    const int warp = tid >> 5;
    const int lane = tid & 31;
    const int c0   = blockIdx.y * CTILE;

    // w fill sources for this thread: rows warp+8i, this lane's float4 column
    const float4* __restrict__ wsrc =
        reinterpret_cast<const float4*>(W) + ((size_t)(e * CC + c0 + warp)) * K4 + lane;
    uint32_t wdst0 = (uint32_t)__cvta_generic_to_shared(&w_st[(size_t)warp * 32 + lane]);
    uint32_t adst0 = (uint32_t)__cvta_generic_to_shared(&a_st[(size_t)warp * 32 + lane]);

    for (int t0 = blockIdx.x * TCH; t0 < cnt; t0 += 2 * TCH) {
        int myt = t0 + warp;
        if (myt >= cnt) myt = cnt - 1;        // tail clamp (dup staging is harmless)
        const float4* asrc =
            reinterpret_cast<const float4*>(act) + (size_t)stok[myt] * K4 + lane;

        unsigned long long acc[RPW][TCH];
#pragma unroll
        for (int r = 0; r < RPW; ++r)
#pragma unroll
            for (int t = 0; t < TCH; ++t) acc[r][t] = 0ull;

        // ---- prime stages 0 .. NSTAGE-2 ----
#pragma unroll
        for (int s = 0; s < NSTAGE - 1; ++s) {
            uint32_t wd = wdst0 + s * (W_ST_F4 * 16);
#pragma unroll
            for (int i = 0; i < 4; ++i)
                cp16(wd + i * (8 * 32 * 16), wsrc + (size_t)(8 * i) * K4 + s * 32);
            cp16(adst0 + s * (A_ST_F4 * 16), asrc + s * 32);
            cp_commit();
        }

#pragma unroll 1
        for (int j = 0; j < JITERS; ++j) {
            cp_wait<NSTAGE - 2>();           // stage j's group complete; 3 in flight
            __syncthreads();                 // visible to all; j-1 reads done

            // refill slot (j-1)%NSTAGE with data for j+NSTAGE-1
            const int jf = j + NSTAGE - 1;
            if (jf < JITERS) {
                const int sf = jf % NSTAGE;
                uint32_t wd = wdst0 + sf * (W_ST_F4 * 16);
#pragma unroll
                for (int i = 0; i < 4; ++i)
                    cp16(wd + i * (8 * 32 * 16), wsrc + (size_t)(8 * i) * K4 + jf * 32);
                cp16(adst0 + sf * (A_ST_F4 * 16), asrc + jf * 32);
            }
            cp_commit();                     // commit every j to keep group counts aligned

            // ---- consume stage j%NSTAGE ----
            const int s = j % NSTAGE;
            const ulonglong2* wb =
                reinterpret_cast<const ulonglong2*>(w_st + (size_t)s * W_ST_F4 + warp * (RPW * 32));
            const ulonglong2* ab =
                reinterpret_cast<const ulonglong2*>(a_st + (size_t)s * A_ST_F4);

            ulonglong2 wv[RPW];
#pragma unroll
            for (int r = 0; r < RPW; ++r) wv[r] = wb[r * 32 + lane];
#pragma unroll
            for (int t = 0; t < TCH; ++t) {
                ulonglong2 av = ab[t * 32 + lane];
#pragma unroll
                for (int r = 0; r < RPW; ++r) {
                    ffma2(acc[r][t], wv[r].x, av.x);
                    ffma2(acc[r][t], wv[r].y, av.y);
                }
            }
        }

        // ---- fold, warp-reduce, store ----
#pragma unroll
        for (int r = 0; r < RPW; ++r) {
#pragma unroll
            for (int t = 0; t < TCH; ++t) {
                float v = pair_sum(acc[r][t]);
                v += __shfl_xor_sync(0xFFFFFFFFu, v, 16);
                v += __shfl_xor_sync(0xFFFFFFFFu, v, 8);
                v += __shfl_xor_sync(0xFFFFFFFFu, v, 4);
                v += __shfl_xor_sync(0xFFFFFFFFu, v, 2);
                v += __shfl_xor_sync(0xFFFFFFFFu, v, 1);
                if (lane == 0 && (t0 + t) < cnt)
                    g_tmp[stok[t0 + t] * CC + c0 + warp * RPW + r] = v;
            }
        }
        __syncthreads();   // all reads of this chunk's stages done before re-prime
    }
}

// ---------------------------------------------------------------------------
__global__ void finalize(const float* __restrict__ residual,
                         const float* __restrict__ bias,
                         const float* __restrict__ ew,
                         const int*  __restrict__ eidx,
                         float* __restrict__ out) {
    const int idx = blockIdx.x * blockDim.x + threadIdx.x;   // over BB*CC/4
    const int b   = idx / (CC / 4);
    const int c4  = idx % (CC / 4);

    const float4* r4 = reinterpret_cast<const float4*>(residual);
    const float4* b4 = reinterpret_cast<const float4*>(bias);
    const float4* t4 = reinterpret_cast<const float4*>(g_tmp);
    float4 v = r4[b * (CC / 4) + c4];
#pragma unroll
    for (int s = 0; s < TOPK; ++s) {
        const int   e = eidx[b * TOPK + s];
        const float w = ew[b * TOPK + s];
        float4 t  = t4[(b * TOPK + s) * (CC / 4) + c4];
        float4 bb = b4[e * (CC / 4) + c4];
        v.x += w * (t.x + bb.x);
        v.y += w * (t.y + bb.y);
        v.z += w * (t.z + bb.z);
        v.w += w * (t.w + bb.w);
    }
    reinterpret_cast<float4*>(out)[b * (CC / 4) + c4] = v;
}

__global__ void epilogue_nop() {}

// ---------------------------------------------------------------------------
extern "C" void kernel_launch(void* const* d_in, const int* in_sizes, int n_in,
                              void* d_out, int out_size) {
    const float* activated      = (const float*)d_in[0];
    const int*   expert_indices = (const int*)  d_in[1];
    const float* expert_weights = (const float*)d_in[2];
    const float* mlp2_weight    = (const float*)d_in[3];
    const float* mlp2_bias      = (const float*)d_in[4];
    const float* residual_x     = (const float*)d_in[5];
    float*       out            = (float*)d_out;

    static bool attr_done = false;
    if (!attr_done) {
        cudaFuncSetAttribute(matvec, cudaFuncAttributeMaxDynamicSharedMemorySize,
                             DYN_BYTES);
        attr_done = true;
    }

    dim3 grid(2, CC / CTILE, EE);   // chunk fastest -> L2 dedup of w re-reads
    matvec<<<grid, WARPS * 32, DYN_BYTES>>>(activated, mlp2_weight,
                                            expert_indices);

    finalize<<<(BB * CC / 4) / 256, 256>>>(residual_x, mlp2_bias,
                                           expert_weights, expert_indices, out);
    epilogue_nop<<<1, 1>>>();
}

// round 10
// speedup vs baseline: 1.8165x; 1.0297x over previous
#include <cuda_runtime.h>
#include <cstdint>

#define BB    64
#define TOPK  2
#define EE    16
#define CC    1024
#define KK    4096
#define NTOK  (BB * TOPK)     // 128

#define WARPS  8
#define RPW    4               // rows per warp
#define TCH    8               // tokens per chunk
#define CTILE  (WARPS * RPW)   // 32 rows per CTA
#define K4     (KK / 4)        // 1024 float4 per row
#define JITERS (K4 / 32)       // 32 k-steps (512B per row per step)
#define NSTAGE 5

// stage = w [CTILE][32] f4 + a [TCH][32] f4
#define W_ST_F4   (CTILE * 32)
#define A_ST_F4   (TCH * 32)
#define DYN_BYTES (NSTAGE * (W_ST_F4 + A_ST_F4) * 16)   // 102400

__device__ float g_tmp[NTOK * CC];

// ---- PTX helpers -----------------------------------------------------------
__device__ __forceinline__ void cp16(uint32_t dst, const void* src) {
    asm volatile("cp.async.cg.shared.global [%0], [%1], 16;"
                 :: "r"(dst), "l"(src) : "memory");
}
__device__ __forceinline__ void cp_commit() {
    asm volatile("cp.async.commit_group;" ::: "memory");
}
template <int N>
__device__ __forceinline__ void cp_wait() {
    asm volatile("cp.async.wait_group %0;" :: "n"(N) : "memory");
}
__device__ __forceinline__ void ffma2(unsigned long long& acc,
                                      unsigned long long w,
                                      unsigned long long a) {
    asm("fma.rn.f32x2 %0, %1, %2, %0;" : "+l"(acc) : "l"(w), "l"(a));
}
__device__ __forceinline__ float pair_sum(unsigned long long p) {
    float lo, hi;
    asm("mov.b64 {%0, %1}, %2;" : "=f"(lo), "=f"(hi) : "l"(p));
    return lo + hi;
}

// ---------------------------------------------------------------------------
// Grouped expert matvec, 5-stage cp.async pipeline for BOTH w and a.
// Grid (2, CC/CTILE=32, EE=16): x = token-chunk (fastest: pair-CTAs sharing a
// weight tile are bid-adjacent -> co-scheduled -> 2nd w read hits L2).
// NEW: per-(y,z) k-phase stagger. Each CTA sweeps k as (j + off) mod 32 so
// CTAs chip-wide are NOT barrier-phase-locked -> DRAM demand is smooth
// instead of bursty. off depends only on (y,z) so the chunk pair keeps the
// same phase (preserves L2 dedup). Deterministic (pure blockIdx function).
// ---------------------------------------------------------------------------
__global__ void __launch_bounds__(256, 2)
matvec(const float* __restrict__ act,
       const float* __restrict__ W,
       const int*  __restrict__ eidx) {
    extern __shared__ float4 dyn[];
    float4* w_st = dyn;                       // [NSTAGE][CTILE][32]
    float4* a_st = dyn + NSTAGE * W_ST_F4;    // [NSTAGE][TCH][32]

    __shared__ int se[NTOK];
    __shared__ int stok[NTOK];

    const int tid = threadIdx.x;
    const int e   = blockIdx.z;

    if (tid < NTOK) se[tid] = eidx[tid];
    __syncthreads();
    int mine = (tid < NTOK) && (se[tid] == e);
    if (mine) {
        int pos = 0;
        for (int j = 0; j < tid; ++j) pos += (se[j] == e) ? 1 : 0;
        stok[pos] = tid;
    }
    const int cnt = __syncthreads_count(mine);
    if (cnt == 0) return;

    const int warp = tid >> 5;
    const int lane = tid & 31;
    const int c0   = blockIdx.y * CTILE;
    // k-phase offset: spreads the 512 (y,z) CTA pairs across all 32 phases
    const int off  = (blockIdx.y + blockIdx.z * 5) & (JITERS - 1);

    // w fill sources for this thread: rows warp+8i, this lane's float4 column
    const float4* __restrict__ wsrc =
        reinterpret_cast<const float4*>(W) + ((size_t)(e * CC + c0 + warp)) * K4 + lane;
    uint32_t wdst0 = (uint32_t)__cvta_generic_to_shared(&w_st[(size_t)warp * 32 + lane]);
    uint32_t adst0 = (uint32_t)__cvta_generic_to_shared(&a_st[(size_t)warp * 32 + lane]);

    for (int t0 = blockIdx.x * TCH; t0 < cnt; t0 += 2 * TCH) {
        int myt = t0 + warp;
        if (myt >= cnt) myt = cnt - 1;        // tail clamp (dup staging is harmless)
        const float4* asrc =
            reinterpret_cast<const float4*>(act) + (size_t)stok[myt] * K4 + lane;

        unsigned long long acc[RPW][TCH];
#pragma unroll
        for (int r = 0; r < RPW; ++r)
#pragma unroll
            for (int t = 0; t < TCH; ++t) acc[r][t] = 0ull;

        // ---- prime stages 0 .. NSTAGE-2 (k-chunks (s+off)&31) ----
#pragma unroll
        for (int s = 0; s < NSTAGE - 1; ++s) {
            const int ks = (s + off) & (JITERS - 1);
            uint32_t wd = wdst0 + s * (W_ST_F4 * 16);
#pragma unroll
            for (int i = 0; i < 4; ++i)
                cp16(wd + i * (8 * 32 * 16), wsrc + (size_t)(8 * i) * K4 + ks * 32);
            cp16(adst0 + s * (A_ST_F4 * 16), asrc + ks * 32);
            cp_commit();
        }

#pragma unroll 1
        for (int j = 0; j < JITERS; ++j) {
            cp_wait<NSTAGE - 2>();           // stage j's group complete; 3 in flight
            __syncthreads();                 // visible to all; j-1 reads done

            // refill slot (j-1)%NSTAGE with k-chunk (j+NSTAGE-1+off)&31
            const int jf = j + NSTAGE - 1;
            if (jf < JITERS) {
                const int kf = (jf + off) & (JITERS - 1);
                const int sf = jf % NSTAGE;
                uint32_t wd = wdst0 + sf * (W_ST_F4 * 16);
#pragma unroll
                for (int i = 0; i < 4; ++i)
                    cp16(wd + i * (8 * 32 * 16), wsrc + (size_t)(8 * i) * K4 + kf * 32);
                cp16(adst0 + sf * (A_ST_F4 * 16), asrc + kf * 32);
            }
            cp_commit();                     // commit every j to keep group counts aligned

            // ---- consume stage j%NSTAGE ----
            const int s = j % NSTAGE;
            const ulonglong2* wb =
                reinterpret_cast<const ulonglong2*>(w_st + (size_t)s * W_ST_F4 + warp * (RPW * 32));
            const ulonglong2* ab =
                reinterpret_cast<const ulonglong2*>(a_st + (size_t)s * A_ST_F4);

            ulonglong2 wv[RPW];
#pragma unroll
            for (int r = 0; r < RPW; ++r) wv[r] = wb[r * 32 + lane];
#pragma unroll
            for (int t = 0; t < TCH; ++t) {
                ulonglong2 av = ab[t * 32 + lane];
#pragma unroll
                for (int r = 0; r < RPW; ++r) {
                    ffma2(acc[r][t], wv[r].x, av.x);
                    ffma2(acc[r][t], wv[r].y, av.y);
                }
            }
        }

        // ---- fold, warp-reduce, store ----
#pragma unroll
        for (int r = 0; r < RPW; ++r) {
#pragma unroll
            for (int t = 0; t < TCH; ++t) {
                float v = pair_sum(acc[r][t]);
                v += __shfl_xor_sync(0xFFFFFFFFu, v, 16);
                v += __shfl_xor_sync(0xFFFFFFFFu, v, 8);
                v += __shfl_xor_sync(0xFFFFFFFFu, v, 4);
                v += __shfl_xor_sync(0xFFFFFFFFu, v, 2);
                v += __shfl_xor_sync(0xFFFFFFFFu, v, 1);
                if (lane == 0 && (t0 + t) < cnt)
                    g_tmp[stok[t0 + t] * CC + c0 + warp * RPW + r] = v;
            }
        }
        __syncthreads();   // all reads of this chunk's stages done before re-prime
    }
}

// ---------------------------------------------------------------------------
__global__ void finalize(const float* __restrict__ residual,
                         const float* __restrict__ bias,
                         const float* __restrict__ ew,
                         const int*  __restrict__ eidx,
                         float* __restrict__ out) {
    const int idx = blockIdx.x * blockDim.x + threadIdx.x;   // over BB*CC/4
    const int b   = idx / (CC / 4);
    const int c4  = idx % (CC / 4);

    const float4* r4 = reinterpret_cast<const float4*>(residual);
    const float4* b4 = reinterpret_cast<const float4*>(bias);
    const float4* t4 = reinterpret_cast<const float4*>(g_tmp);
    float4 v = r4[b * (CC / 4) + c4];
#pragma unroll
    for (int s = 0; s < TOPK; ++s) {
        const int   e = eidx[b * TOPK + s];
        const float w = ew[b * TOPK + s];
        float4 t  = t4[(b * TOPK + s) * (CC / 4) + c4];
        float4 bb = b4[e * (CC / 4) + c4];
        v.x += w * (t.x + bb.x);
        v.y += w * (t.y + bb.y);
        v.z += w * (t.z + bb.z);
        v.w += w * (t.w + bb.w);
    }
    reinterpret_cast<float4*>(out)[b * (CC / 4) + c4] = v;
}

__global__ void epilogue_nop() {}

// ---------------------------------------------------------------------------
extern "C" void kernel_launch(void* const* d_in, const int* in_sizes, int n_in,
                              void* d_out, int out_size) {
    const float* activated      = (const float*)d_in[0];
    const int*   expert_indices = (const int*)  d_in[1];
    const float* expert_weights = (const float*)d_in[2];
    const float* mlp2_weight    = (const float*)d_in[3];
    const float* mlp2_bias      = (const float*)d_in[4];
    const float* residual_x     = (const float*)d_in[5];
    float*       out            = (float*)d_out;

    static bool attr_done = false;
    if (!attr_done) {
        cudaFuncSetAttribute(matvec, cudaFuncAttributeMaxDynamicSharedMemorySize,
                             DYN_BYTES);
        attr_done = true;
    }

    dim3 grid(2, CC / CTILE, EE);   // chunk fastest -> L2 dedup of w re-reads
    matvec<<<grid, WARPS * 32, DYN_BYTES>>>(activated, mlp2_weight,
                                            expert_indices);

    finalize<<<(BB * CC / 4) / 256, 256>>>(residual_x, mlp2_bias,
                                           expert_weights, expert_indices, out);
    epilogue_nop<<<1, 1>>>();
}

// round 11
// speedup vs baseline: 1.8703x; 1.0296x over previous
#include <cuda_runtime.h>
#include <cstdint>

#define BB    64
#define TOPK  2
#define EE    16
#define CC    1024
#define KK    4096
#define NTOK  (BB * TOPK)     // 128

#define WARPS  4               // 128-thread CTA: 4-warp convergence domain
#define RPW    4               // rows per warp
#define TCH    8               // tokens per chunk
#define CTILE  (WARPS * RPW)   // 16 rows per CTA
#define K4     (KK / 4)        // 1024 float4 per row
#define JITERS (K4 / 32)       // 32 k-steps (512B per row per step)
#define NSTAGE 4               // power of two: ring math is & 3

// stage = w [CTILE][32] f4 + a [TCH][32] f4 = 768 f4 = 12KB
#define W_ST_F4   (CTILE * 32)                       // 512
#define A_ST_F4   (TCH * 32)                         // 256
#define ST_F4     (W_ST_F4 + A_ST_F4)                // 768
#define ST_BYTES  (ST_F4 * 16)                       // 12288
#define DYN_BYTES (NSTAGE * ST_BYTES)                // 49152

__device__ float g_tmp[NTOK * CC];

// ---- PTX helpers -----------------------------------------------------------
__device__ __forceinline__ void cp16(uint32_t dst, const void* src) {
    asm volatile("cp.async.cg.shared.global [%0], [%1], 16;"
                 :: "r"(dst), "l"(src) : "memory");
}
__device__ __forceinline__ void cp_commit() {
    asm volatile("cp.async.commit_group;" ::: "memory");
}
template <int N>
__device__ __forceinline__ void cp_wait() {
    asm volatile("cp.async.wait_group %0;" :: "n"(N) : "memory");
}
__device__ __forceinline__ void ffma2(unsigned long long& acc,
                                      unsigned long long w,
                                      unsigned long long a) {
    asm("fma.rn.f32x2 %0, %1, %2, %0;" : "+l"(acc) : "l"(w), "l"(a));
}
__device__ __forceinline__ float pair_sum(unsigned long long p) {
    float lo, hi;
    asm("mov.b64 {%0, %1}, %2;" : "=f"(lo), "=f"(hi) : "l"(p));
    return lo + hi;
}

// ---------------------------------------------------------------------------
// Grouped expert matvec — small-CTA variant.
// Grid (2, CC/CTILE=64, EE=16): x = token-chunk (fastest: pair CTAs sharing a
// weight tile are bid-adjacent -> 2nd read hits L2), y = c-tile, z = expert.
// Block 128 (4 warps), 4 CTAs/SM: halves the barrier convergence domain and
// quadruples independent DRAM streams per SM vs the 256-thread version.
// 4-stage (pow2) cp.async ring for w AND a; per-(y,z) k-phase stagger.
// Fill per thread per j: 4 w rows {warp+4i} + 2 a tokens {2*warp, 2*warp+1}.
// Consume: warp owns rows warp*4..+3 x all 8 tokens (64 FFMA2 / j).
// ---------------------------------------------------------------------------
__global__ void __launch_bounds__(128, 4)
matvec(const float* __restrict__ act,
       const float* __restrict__ W,
       const int*  __restrict__ eidx) {
    extern __shared__ float4 st[];            // [NSTAGE][768]

    __shared__ int se[NTOK];
    __shared__ int stok[NTOK];

    const int tid = threadIdx.x;
    const int e   = blockIdx.z;

    se[tid] = eidx[tid];                      // 128 threads == NTOK
    __syncthreads();
    int mine = (se[tid] == e);
    if (mine) {
        int pos = 0;
        for (int j = 0; j < tid; ++j) pos += (se[j] == e) ? 1 : 0;
        stok[pos] = tid;
    }
    const int cnt = __syncthreads_count(mine);
    if (cnt == 0) return;

    const int warp = tid >> 5;
    const int lane = tid & 31;
    const int c0   = blockIdx.y * CTILE;
    // k-phase stagger: decorrelates CTA DRAM phases; same for the x-pair
    const int off  = (blockIdx.y + blockIdx.z * 5) & (JITERS - 1);

    // w fill: rows {c0+warp+4i}, this lane's float4 column
    const float4* __restrict__ wsrc =
        reinterpret_cast<const float4*>(W) + ((size_t)(e * CC + c0 + warp)) * K4 + lane;
    const uint32_t wdst0 =
        (uint32_t)__cvta_generic_to_shared(&st[(size_t)warp * 32 + lane]);
    const uint32_t adst0 =
        (uint32_t)__cvta_generic_to_shared(&st[(size_t)W_ST_F4 + warp * 64 + lane]);

    for (int t0 = blockIdx.x * TCH; t0 < cnt; t0 += 2 * TCH) {
        // a fill: tokens t0+2*warp, t0+2*warp+1 (tail-clamped; dup harmless)
        int ta0 = t0 + 2 * warp;     if (ta0 >= cnt) ta0 = cnt - 1;
        int ta1 = t0 + 2 * warp + 1; if (ta1 >= cnt) ta1 = cnt - 1;
        const float4* a0 =
            reinterpret_cast<const float4*>(act) + (size_t)stok[ta0] * K4 + lane;
        const float4* a1 =
            reinterpret_cast<const float4*>(act) + (size_t)stok[ta1] * K4 + lane;

        unsigned long long acc[RPW][TCH];
#pragma unroll
        for (int r = 0; r < RPW; ++r)
#pragma unroll
            for (int t = 0; t < TCH; ++t) acc[r][t] = 0ull;

        // ---- prime stages 0 .. NSTAGE-2 ----
#pragma unroll
        for (int s = 0; s < NSTAGE - 1; ++s) {
            const int ks = (s + off) & (JITERS - 1);
            const uint32_t d = wdst0 + s * ST_BYTES;
#pragma unroll
            for (int i = 0; i < 4; ++i)
                cp16(d + i * (4 * 512), wsrc + (size_t)(4 * i) * K4 + ks * 32);
            cp16(adst0 + s * ST_BYTES,       a0 + ks * 32);
            cp16(adst0 + s * ST_BYTES + 512, a1 + ks * 32);
            cp_commit();
        }

#pragma unroll 1
        for (int j = 0; j < JITERS; ++j) {
            cp_wait<NSTAGE - 2>();           // stage j ready; 2 groups in flight
            __syncthreads();                 // 4-warp convergence only

            const int jf = j + NSTAGE - 1;
            if (jf < JITERS) {
                const int kf = (jf + off) & (JITERS - 1);
                const uint32_t d = wdst0 + (jf & (NSTAGE - 1)) * ST_BYTES;
#pragma unroll
                for (int i = 0; i < 4; ++i)
                    cp16(d + i * (4 * 512), wsrc + (size_t)(4 * i) * K4 + kf * 32);
                const uint32_t da = adst0 + (jf & (NSTAGE - 1)) * ST_BYTES;
                cp16(da,       a0 + kf * 32);
                cp16(da + 512, a1 + kf * 32);
            }
            cp_commit();                     // commit every j: group counts aligned

            // ---- consume stage j & 3 ----
            const ulonglong2* base = reinterpret_cast<const ulonglong2*>(
                st + (size_t)(j & (NSTAGE - 1)) * ST_F4);
            const ulonglong2* wb = base + (warp * RPW) * 32 + lane;
            const ulonglong2* ab = base + W_ST_F4 + lane;

            ulonglong2 wv[RPW];
#pragma unroll
            for (int r = 0; r < RPW; ++r) wv[r] = wb[r * 32];
#pragma unroll
            for (int t = 0; t < TCH; ++t) {
                ulonglong2 av = ab[t * 32];
#pragma unroll
                for (int r = 0; r < RPW; ++r) {
                    ffma2(acc[r][t], wv[r].x, av.x);
                    ffma2(acc[r][t], wv[r].y, av.y);
                }
            }
        }

        // ---- fold, warp-reduce, store ----
#pragma unroll
        for (int r = 0; r < RPW; ++r) {
#pragma unroll
            for (int t = 0; t < TCH; ++t) {
                float v = pair_sum(acc[r][t]);
                v += __shfl_xor_sync(0xFFFFFFFFu, v, 16);
                v += __shfl_xor_sync(0xFFFFFFFFu, v, 8);
                v += __shfl_xor_sync(0xFFFFFFFFu, v, 4);
                v += __shfl_xor_sync(0xFFFFFFFFu, v, 2);
                v += __shfl_xor_sync(0xFFFFFFFFu, v, 1);
                if (lane == 0 && (t0 + t) < cnt)
                    g_tmp[stok[t0 + t] * CC + c0 + warp * RPW + r] = v;
            }
        }
        __syncthreads();   // all stage reads done before next chunk re-primes
    }
}

// ---------------------------------------------------------------------------
__global__ void finalize(const float* __restrict__ residual,
                         const float* __restrict__ bias,
                         const float* __restrict__ ew,
                         const int*  __restrict__ eidx,
                         float* __restrict__ out) {
    const int idx = blockIdx.x * blockDim.x + threadIdx.x;   // over BB*CC/4
    const int b   = idx / (CC / 4);
    const int c4  = idx % (CC / 4);

    const float4* r4 = reinterpret_cast<const float4*>(residual);
    const float4* b4 = reinterpret_cast<const float4*>(bias);
    const float4* t4 = reinterpret_cast<const float4*>(g_tmp);
    float4 v = r4[b * (CC / 4) + c4];
#pragma unroll
    for (int s = 0; s < TOPK; ++s) {
        const int   e = eidx[b * TOPK + s];
        const float w = ew[b * TOPK + s];
        float4 t  = t4[(b * TOPK + s) * (CC / 4) + c4];
        float4 bb = b4[e * (CC / 4) + c4];
        v.x += w * (t.x + bb.x);
        v.y += w * (t.y + bb.y);
        v.z += w * (t.z + bb.z);
        v.w += w * (t.w + bb.w);
    }
    reinterpret_cast<float4*>(out)[b * (CC / 4) + c4] = v;
}

__global__ void epilogue_nop() {}

// ---------------------------------------------------------------------------
extern "C" void kernel_launch(void* const* d_in, const int* in_sizes, int n_in,
                              void* d_out, int out_size) {
    const float* activated      = (const float*)d_in[0];
    const int*   expert_indices = (const int*)  d_in[1];
    const float* expert_weights = (const float*)d_in[2];
    const float* mlp2_weight    = (const float*)d_in[3];
    const float* mlp2_bias      = (const float*)d_in[4];
    const float* residual_x     = (const float*)d_in[5];
    float*       out            = (float*)d_out;

    static bool attr_done = false;
    if (!attr_done) {
        cudaFuncSetAttribute(matvec, cudaFuncAttributeMaxDynamicSharedMemorySize,
                             DYN_BYTES);
        attr_done = true;
    }

    dim3 grid(2, CC / CTILE, EE);   // chunk fastest -> L2 dedup of w re-reads
    matvec<<<grid, WARPS * 32, DYN_BYTES>>>(activated, mlp2_weight,
                                            expert_indices);

    finalize<<<(BB * CC / 4) / 256, 256>>>(residual_x, mlp2_bias,
                                           expert_weights, expert_indices, out);
    epilogue_nop<<<1, 1>>>();
}